// round 16
// baseline (speedup 1.0000x reference)
#include <cuda_runtime.h>
#include <cuda_bf16.h>
#include <cuda_fp16.h>
#include <stdint.h>
#include <math.h>

#define N_NODES 50000
#define N_EDGES 200000
#define D_IN    128
#define DD      256
#define N_LAYERS 4
#define N_RELS  4
#define NUM_M   1024
#define NUM_R   64
#define N_ALL   (NUM_R + NUM_M)
#define GW      1280
#define MPAD    (N_NODES + 128)
#define HPAD    1152

__device__ __half g_G[(size_t)N_NODES * GW];
__device__ __half g_Wfh[N_LAYERS * GW * 256];
__device__ __half g_nWfh[256 * D_IN];
__device__ __half g_xf[(size_t)MPAD * D_IN];
__device__ __half g_Af[(size_t)MPAD * DD];
__device__ __half g_pqWfh[1024 * 256];
__device__ __half g_pqWfl[1024 * 256];
__device__ __half g_w1fh[256 * 512];
__device__ __half g_w1fl[256 * 512];
__device__ __half g_Hf[HPAD * DD];
__device__ __half g_repf[HPAD * 512];
__device__ float g_bcat[1024];
__device__ int   g_cnt[N_RELS * N_NODES];
__device__ int   g_deg[N_NODES];
__device__ int   g_off[N_NODES + 1];
__device__ int   g_cursor[N_NODES];
__device__ uint2 g_epack[N_EDGES];
__device__ int   g_start[NUM_M + 1];
__device__ float g_puqz[N_ALL * 1024];
__device__ float g_u[N_ALL * DD];
__device__ float g_zM[NUM_M * DD];
__device__ float g_zR[NUM_R * DD];
__device__ float g_An[NUM_M * NUM_R];
__device__ float g_hid[HPAD * 256];
__device__ float g_acc[4];

__host__ __device__ __forceinline__ uint32_t rotl32(uint32_t x, int d) {
    return (x << d) | (x >> (32 - d));
}
__host__ __device__ __forceinline__ void tf2x32(uint32_t k0, uint32_t k1,
                                                uint32_t x0, uint32_t x1,
                                                uint32_t& o0, uint32_t& o1) {
    uint32_t ks2 = k0 ^ k1 ^ 0x1BD11BDAu;
    x0 += k0; x1 += k1;
#define TF_RND(R) { x0 += x1; x1 = rotl32(x1, R); x1 ^= x0; }
    TF_RND(13) TF_RND(15) TF_RND(26) TF_RND(6)
    x0 += k1;  x1 += ks2 + 1u;
    TF_RND(17) TF_RND(29) TF_RND(16) TF_RND(24)
    x0 += ks2; x1 += k0 + 2u;
    TF_RND(13) TF_RND(15) TF_RND(26) TF_RND(6)
    x0 += k0;  x1 += k1 + 3u;
    TF_RND(17) TF_RND(29) TF_RND(16) TF_RND(24)
    x0 += k1;  x1 += ks2 + 4u;
    TF_RND(13) TF_RND(15) TF_RND(26) TF_RND(6)
    x0 += ks2; x1 += k0 + 5u;
#undef TF_RND
    o0 = x0; o1 = x1;
}
__device__ __forceinline__ uint32_t rbits(uint32_t k0, uint32_t k1, uint32_t i) {
    uint32_t o0, o1; tf2x32(k0, k1, 0u, i, o0, o1); return o0 ^ o1;
}
__device__ __forceinline__ float erfinv_xla(float x) {
    float w = -log1pf(-x * x), p;
    if (w < 5.0f) {
        w -= 2.5f;
        p = 2.81022636e-08f;
        p = fmaf(p, w, 3.43273939e-07f);  p = fmaf(p, w, -3.5233877e-06f);
        p = fmaf(p, w, -4.39150654e-06f); p = fmaf(p, w, 0.00021858087f);
        p = fmaf(p, w, -0.00125372503f);  p = fmaf(p, w, -0.00417768164f);
        p = fmaf(p, w, 0.246640727f);     p = fmaf(p, w, 1.50140941f);
    } else {
        w = sqrtf(w) - 3.0f;
        p = -0.000200214257f;
        p = fmaf(p, w, 0.000100950558f);  p = fmaf(p, w, 0.00134934322f);
        p = fmaf(p, w, -0.00367342844f);  p = fmaf(p, w, 0.00573950773f);
        p = fmaf(p, w, -0.0076224613f);   p = fmaf(p, w, 0.00943887047f);
        p = fmaf(p, w, 1.00167406f);      p = fmaf(p, w, 2.83297682f);
    }
    return p * x;
}
__device__ __forceinline__ float u01(uint32_t b) {
    return __uint_as_float((b >> 9) | 0x3f800000u) - 1.0f;
}
__device__ __forceinline__ float nrm(uint32_t b) {
    const float LO = -0.99999994f;
    float v = u01(b) * 2.0f + LO;
    v = fmaxf(LO, v);
    return 1.41421356f * erfinv_xla(v);
}
__device__ __forceinline__ float unif(uint32_t b) {
    const float MN = 1e-06f;
    float v = u01(b) * (0.999999f - MN) + MN;
    return fmaxf(MN, v);
}

__global__ void k_zero_init() {
    int i = blockIdx.x * blockDim.x + threadIdx.x;
    if (i < N_RELS * N_NODES) g_cnt[i] = 0;
    if (i < N_NODES) g_deg[i] = 0;
    if (i < 4) g_acc[i] = 0.0f;
}
__global__ void k_count(const int* __restrict__ ei, const int* __restrict__ et) {
    int e = blockIdx.x * blockDim.x + threadIdx.x;
    if (e >= N_EDGES) return;
    int d = ei[N_EDGES + e];
    atomicAdd(&g_cnt[et[e] * N_NODES + d], 1);
    atomicAdd(&g_deg[d], 1);
}
__global__ void k_scan() {
    __shared__ int part[1024];
    int tid = threadIdx.x;
    const int chunk = (N_NODES + 1023) / 1024;
    int lo = tid * chunk, hi = min(lo + chunk, N_NODES);
    int s = 0;
    for (int i = lo; i < hi; i++) s += g_deg[i];
    part[tid] = s;
    __syncthreads();
    for (int o = 1; o < 1024; o <<= 1) {
        int v = (tid >= o) ? part[tid - o] : 0;
        __syncthreads(); part[tid] += v; __syncthreads();
    }
    int run = part[tid] - s;
    for (int i = lo; i < hi; i++) { g_off[i] = run; g_cursor[i] = run; run += g_deg[i]; }
    if (tid == 1023) g_off[N_NODES] = run;
}
__global__ void k_scatter(const int* __restrict__ ei, const int* __restrict__ et) {
    int e = blockIdx.x * blockDim.x + threadIdx.x;
    if (e >= N_EDGES) return;
    int sn = ei[e], d = ei[N_EDGES + e], r = et[e];
    int p = atomicAdd(&g_cursor[d], 1);
    float inv = 1.0f / (float)g_cnt[r * N_NODES + d];
    g_epack[p] = make_uint2((uint32_t)(sn * GW + 256 + (r << 8)), __float_as_uint(inv));
}

__global__ void k_prep(const float* __restrict__ x, const float* __restrict__ nodeW,
                       const float* __restrict__ Wroot, const float* __restrict__ Wr,
                       const float* __restrict__ puW, const float* __restrict__ qzW,
                       const float* __restrict__ W1, const float* __restrict__ puB,
                       const float* __restrict__ qzB, const int* __restrict__ batch,
                       const float* __restrict__ HR) {
    const int nF = N_NODES * D_IN;
    const int nA = N_LAYERS * GW * 256;
    const int nB = 256 * D_IN;
    const int nC = 1024 * 256;
    const int nE = 256 * 512;
    int i = blockIdx.x * blockDim.x + threadIdx.x;
    if (i < nF) { g_xf[i] = __float2half_rn(x[i]); return; }
    i -= nF;
    if (i < nA) {
        int l = i / (GW * 256), rem = i % (GW * 256);
        int n = rem / 256, k = rem % 256;
        float v;
        if (n < 256) v = Wroot[((size_t)l * 256 + k) * 256 + n];
        else {
            int r = (n >> 8) - 1, h = n & 255;
            v = Wr[(((size_t)l * 4 + r) * 256 + k) * 256 + h];
        }
        g_Wfh[i] = __float2half_rn(v);
        return;
    }
    i -= nA;
    if (i < nB) {
        int n = i / D_IN, k = i % D_IN;
        g_nWfh[i] = __float2half_rn(nodeW[(size_t)k * 256 + n]);
        return;
    }
    i -= nB;
    if (i < nC) {
        int n = i / 256, k = i % 256;
        float v = (n < 512) ? puW[(size_t)k * 512 + n] : qzW[(size_t)k * 512 + (n - 512)];
        __half hi = __float2half_rn(v);
        g_pqWfh[i] = hi;
        g_pqWfl[i] = __float2half_rn(v - __half2float(hi));
        return;
    }
    i -= nC;
    if (i < nE) {
        int n = i / 512, k = i % 512;
        float v = W1[(size_t)k * 256 + n];
        __half hi = __float2half_rn(v);
        g_w1fh[i] = hi;
        g_w1fl[i] = __float2half_rn(v - __half2float(hi));
        return;
    }
    i -= nE;
    if (i < 1024) { g_bcat[i] = (i < 512) ? puB[i] : qzB[i - 512]; return; }
    i -= 1024;
    if (i <= NUM_M) {
        int lo = 0, hi = N_NODES;
        while (lo < hi) { int mid = (lo + hi) >> 1; if (batch[mid] < i) lo = mid + 1; else hi = mid; }
        g_start[i] = lo;
        return;
    }
    i -= (NUM_M + 1);
    if (i < NUM_R * DD) {
        g_Hf[i] = __float2half_rn(fmaxf(HR[i], 0.f));
    }
}

__device__ __forceinline__ void ldm4(uint32_t a, uint32_t& r0, uint32_t& r1,
                                     uint32_t& r2, uint32_t& r3) {
    asm volatile("ldmatrix.sync.aligned.m8n8.x4.shared.b16 {%0,%1,%2,%3}, [%4];"
                 : "=r"(r0), "=r"(r1), "=r"(r2), "=r"(r3) : "r"(a));
}
__device__ __forceinline__ void mma_fp(float* c, const uint32_t* a, const uint32_t* b) {
    asm volatile("mma.sync.aligned.m16n8k16.row.col.f32.f16.f16.f32 "
                 "{%0,%1,%2,%3},{%4,%5,%6,%7},{%8,%9},{%0,%1,%2,%3};"
                 : "+f"(c[0]), "+f"(c[1]), "+f"(c[2]), "+f"(c[3])
                 : "r"(a[0]), "r"(a[1]), "r"(a[2]), "r"(a[3]), "r"(b[0]), "r"(b[1]));
}
__device__ __forceinline__ void cp16(uint32_t dst, const void* src) {
    asm volatile("cp.async.cg.shared.global [%0], [%1], 16;" :: "r"(dst), "l"(src));
}

// ===== fp16 1-term GEMM, BM=BN=128, BK=32, 3 stages, 2 CTA/SM =====
#define LOAD_STAGE_F(s, kq)                                            \
    do {                                                               \
        uint32_t st_ = smq + (s) * 20480;                              \
        _Pragma("unroll")                                              \
        for (int q_ = 0; q_ < 2; q_++) {                               \
            int col_ = (c0 + q_) * 8;                                  \
            uint32_t dd_ = st_ + (row * 40 + col_) * 2;                \
            cp16(dd_,         Agf + (kq) + col_);                      \
            cp16(dd_ + 10240, Bgh + (kq) + col_);                      \
        }                                                              \
    } while (0)

__global__ void __launch_bounds__(256, 2)
k_fmma(const __half* __restrict__ Af, const __half* __restrict__ Bh,
       const float* __restrict__ bias, float* __restrict__ C,
       __half* __restrict__ oF, int M, int N, int K, int relu_out) {
    extern __shared__ __align__(16) __half dsmf[];
    uint32_t smq = (uint32_t)__cvta_generic_to_shared(dsmf);
    int tid = threadIdx.x, lane = tid & 31, wid = tid >> 5;
    int wm = (wid >> 2) * 64, wn = (wid & 3) * 32;
    int bm = blockIdx.y * 128, bn = blockIdx.x * 128;
    int row = tid >> 1, c0 = (tid & 1) * 2;
    const __half* Agf = Af + (size_t)(bm + row) * K;
    const __half* Bgh = Bh + (size_t)(bn + row) * K;

    float acc[4][4][4];
#pragma unroll
    for (int i = 0; i < 4; i++)
#pragma unroll
        for (int j = 0; j < 4; j++)
#pragma unroll
            for (int q = 0; q < 4; q++) acc[i][j][q] = 0.f;

    LOAD_STAGE_F(0, 0);
    asm volatile("cp.async.commit_group;");
    if (32 < K) LOAD_STAGE_F(1, 32);
    asm volatile("cp.async.commit_group;");

    int cur = 0;
    for (int k0 = 0; k0 < K; k0 += 32) {
        int pre = k0 + 64;
        if (pre < K) {
            int s2 = cur + 2; if (s2 >= 3) s2 -= 3;
            LOAD_STAGE_F(s2, pre);
        }
        asm volatile("cp.async.commit_group;");
        asm volatile("cp.async.wait_group 2;");
        __syncthreads();
        uint32_t st = smq + cur * 20480;
#pragma unroll
        for (int kk = 0; kk < 32; kk += 16) {
            uint32_t bh[4][2];
            int brow = wn + (lane & 7) + ((lane >> 4) & 1) * 8;
            int bcol = kk + ((lane >> 3) & 1) * 8;
#pragma unroll
            for (int nb = 0; nb < 2; nb++) {
                uint32_t off = ((brow + nb * 16) * 40 + bcol) * 2;
                ldm4(st + 10240 + off, bh[2 * nb][0], bh[2 * nb][1], bh[2 * nb + 1][0], bh[2 * nb + 1][1]);
            }
            int arow = wm + (lane & 7) + ((lane >> 3) & 1) * 8;
            int acol = kk + ((lane >> 4) & 1) * 8;
#pragma unroll
            for (int mf = 0; mf < 4; mf++) {
                uint32_t a[4];
                uint32_t off = ((arow + mf * 16) * 40 + acol) * 2;
                ldm4(st + off, a[0], a[1], a[2], a[3]);
#pragma unroll
                for (int nf = 0; nf < 4; nf++)
                    mma_fp(acc[mf][nf], a, bh[nf]);
            }
        }
        __syncthreads();
        cur++; if (cur >= 3) cur = 0;
    }
#pragma unroll
    for (int mf = 0; mf < 4; mf++)
#pragma unroll
        for (int nf = 0; nf < 4; nf++) {
            int r0 = bm + wm + mf * 16 + (lane >> 2);
            int c0o = bn + wn + nf * 8 + (lane & 3) * 2;
#pragma unroll
            for (int h = 0; h < 2; h++) {
                int r = r0 + h * 8;
                if (r >= M) continue;
                float v0 = acc[mf][nf][2 * h], v1 = acc[mf][nf][2 * h + 1];
                if (bias) { v0 += bias[c0o]; v1 += bias[c0o + 1]; }
                if (relu_out) { v0 = fmaxf(v0, 0.f); v1 = fmaxf(v1, 0.f); }
                if (oF) {
                    *(__half2*)(oF + (size_t)r * N + c0o) = __floats2half2_rn(v0, v1);
                } else {
                    *(float2*)(C + (size_t)r * N + c0o) = make_float2(v0, v1);
                }
            }
        }
}

// ===== fp16 2-term GEMM for tail: A fp16, B hi/lo fp16. BK=32, 3 stages, 2 CTA/SM =====
#define LOAD_STAGE_2(s, kq)                                            \
    do {                                                               \
        uint32_t st_ = sm2 + (s) * 30720;                              \
        _Pragma("unroll")                                              \
        for (int q_ = 0; q_ < 2; q_++) {                               \
            int col_ = (c0 + q_) * 8;                                  \
            uint32_t dd_ = st_ + (row * 40 + col_) * 2;                \
            cp16(dd_,         Agf + (kq) + col_);                      \
            cp16(dd_ + 10240, Bgh + (kq) + col_);                      \
            cp16(dd_ + 20480, Bgl + (kq) + col_);                      \
        }                                                              \
    } while (0)

__global__ void __launch_bounds__(256, 2)
k_fmma2(const __half* __restrict__ Af, const __half* __restrict__ Bh,
        const __half* __restrict__ Bl, const float* __restrict__ bias,
        float* __restrict__ C, int M, int N, int K, int relu_out) {
    extern __shared__ __align__(16) __half dsm2[];
    uint32_t sm2 = (uint32_t)__cvta_generic_to_shared(dsm2);
    int tid = threadIdx.x, lane = tid & 31, wid = tid >> 5;
    int wm = (wid >> 2) * 64, wn = (wid & 3) * 32;
    int bm = blockIdx.y * 128, bn = blockIdx.x * 128;
    int row = tid >> 1, c0 = (tid & 1) * 2;
    const __half* Agf = Af + (size_t)(bm + row) * K;
    const __half* Bgh = Bh + (size_t)(bn + row) * K;
    const __half* Bgl = Bl + (size_t)(bn + row) * K;

    float acc[4][4][4];
#pragma unroll
    for (int i = 0; i < 4; i++)
#pragma unroll
        for (int j = 0; j < 4; j++)
#pragma unroll
            for (int q = 0; q < 4; q++) acc[i][j][q] = 0.f;

    LOAD_STAGE_2(0, 0);
    asm volatile("cp.async.commit_group;");
    if (32 < K) LOAD_STAGE_2(1, 32);
    asm volatile("cp.async.commit_group;");

    int cur = 0;
    for (int k0 = 0; k0 < K; k0 += 32) {
        int pre = k0 + 64;
        if (pre < K) {
            int s2 = cur + 2; if (s2 >= 3) s2 -= 3;
            LOAD_STAGE_2(s2, pre);
        }
        asm volatile("cp.async.commit_group;");
        asm volatile("cp.async.wait_group 2;");
        __syncthreads();
        uint32_t st = sm2 + cur * 30720;
#pragma unroll
        for (int kk = 0; kk < 32; kk += 16) {
            uint32_t bh[4][2], bl[4][2];
            int brow = wn + (lane & 7) + ((lane >> 4) & 1) * 8;
            int bcol = kk + ((lane >> 3) & 1) * 8;
#pragma unroll
            for (int nb = 0; nb < 2; nb++) {
                uint32_t off = ((brow + nb * 16) * 40 + bcol) * 2;
                ldm4(st + 10240 + off, bh[2 * nb][0], bh[2 * nb][1], bh[2 * nb + 1][0], bh[2 * nb + 1][1]);
                ldm4(st + 20480 + off, bl[2 * nb][0], bl[2 * nb][1], bl[2 * nb + 1][0], bl[2 * nb + 1][1]);
            }
            int arow = wm + (lane & 7) + ((lane >> 3) & 1) * 8;
            int acol = kk + ((lane >> 4) & 1) * 8;
#pragma unroll
            for (int mf = 0; mf < 4; mf++) {
                uint32_t a[4];
                uint32_t off = ((arow + mf * 16) * 40 + acol) * 2;
                ldm4(st + off, a[0], a[1], a[2], a[3]);
#pragma unroll
                for (int nf = 0; nf < 4; nf++) {
                    mma_fp(acc[mf][nf], a, bh[nf]);
                    mma_fp(acc[mf][nf], a, bl[nf]);
                }
            }
        }
        __syncthreads();
        cur++; if (cur >= 3) cur = 0;
    }
#pragma unroll
    for (int mf = 0; mf < 4; mf++)
#pragma unroll
        for (int nf = 0; nf < 4; nf++) {
            int r0 = bm + wm + mf * 16 + (lane >> 2);
            int c0o = bn + wn + nf * 8 + (lane & 3) * 2;
#pragma unroll
            for (int h = 0; h < 2; h++) {
                int r = r0 + h * 8;
                if (r >= M) continue;
                float v0 = acc[mf][nf][2 * h], v1 = acc[mf][nf][2 * h + 1];
                if (bias) { v0 += bias[c0o]; v1 += bias[c0o + 1]; }
                if (relu_out) { v0 = fmaxf(v0, 0.f); v1 = fmaxf(v1, 0.f); }
                *(float2*)(C + (size_t)r * N + c0o) = make_float2(v0, v1);
            }
        }
}

// aggregation over fp16 G, 4 warps per node (each warp owns 64 cols; 2 cols/lane)
__global__ void k_agg(const float* __restrict__ bias, __half* __restrict__ ofh, int relu) {
    int gw = (blockIdx.x * blockDim.x + threadIdx.x) >> 5;
    int lane = threadIdx.x & 31;
    int d = gw >> 2;
    int quarter = gw & 3;
    if (d >= N_NODES) return;
    int cb = quarter * 64 + lane * 2;
    float a0, a1;
    {
        __half2 base = *(const __half2*)(g_G + (size_t)d * GW + cb);
        float2 bf = __half22float2(base);
        float2 bb = *(const float2*)(bias + cb);
        a0 = bf.x + bb.x;
        a1 = bf.y + bb.y;
    }
    int s = g_off[d], e = g_off[d + 1];
    int i = s;
#define AGG_EDGE(P)                                                     \
    {                                                                   \
        __half2 gv = *(const __half2*)(g_G + (P).x + cb);               \
        float inv = __uint_as_float((P).y);                             \
        float2 f = __half22float2(gv);                                  \
        a0 = fmaf(f.x, inv, a0);                                        \
        a1 = fmaf(f.y, inv, a1);                                        \
    }
    for (; i + 8 <= e; i += 8) {
        uint2 p0 = g_epack[i],     p1 = g_epack[i + 1];
        uint2 p2 = g_epack[i + 2], p3 = g_epack[i + 3];
        uint2 p4 = g_epack[i + 4], p5 = g_epack[i + 5];
        uint2 p6 = g_epack[i + 6], p7 = g_epack[i + 7];
        AGG_EDGE(p0) AGG_EDGE(p1) AGG_EDGE(p2) AGG_EDGE(p3)
        AGG_EDGE(p4) AGG_EDGE(p5) AGG_EDGE(p6) AGG_EDGE(p7)
    }
    for (; i < e; i++) {
        uint2 p0 = g_epack[i];
        AGG_EDGE(p0)
    }
#undef AGG_EDGE
    if (relu) { a0 = fmaxf(a0, 0.f); a1 = fmaxf(a1, 0.f); }
    *(__half2*)(ofh + (size_t)d * DD + cb) = __floats2half2_rn(a0, a1);
}

__global__ void k_gmean() {
    int m = blockIdx.x, c = threadIdx.x;
    int s = g_start[m], e = g_start[m + 1];
    float acc = 0.f;
    for (int n = s; n < e; n++) acc += __half2float(g_Af[(size_t)n * DD + c]);
    float v = fmaxf(acc / fmaxf((float)(e - s), 1.0f), 0.f);
    g_Hf[(size_t)(NUM_R + m) * DD + c] = __float2half_rn(v);
}

__global__ void k_sample_all(unsigned ku0, unsigned ku1, unsigned kzm0, unsigned kzm1,
                             unsigned kzr0, unsigned kzr1) {
    int i = blockIdx.x * blockDim.x + threadIdx.x;
    const int NU = N_ALL * DD, NZM = NUM_M * DD, NZR = NUM_R * DD;
    float v;
    int rrow, rcol;
    if (i < NU) {
        int row = i >> 8, col = i & 255;
        v = g_puqz[row * 1024 + col] +
            expf(g_puqz[row * 1024 + 256 + col]) * nrm(rbits(ku0, ku1, i));
        g_u[i] = v;
        rrow = (row < NUM_R) ? (NUM_M + row) : (row - NUM_R);
        rcol = 256 + col;
    } else if (i < NU + NZM) {
        int j = i - NU;
        int m = j >> 8, col = j & 255;
        int r = (NUM_R + m) * 1024 + 512;
        v = g_puqz[r + col] + expf(g_puqz[r + 256 + col]) * nrm(rbits(kzm0, kzm1, j));
        g_zM[j] = v;
        rrow = m; rcol = col;
    } else if (i < NU + NZM + NZR) {
        int j = i - NU - NZM;
        int r = (j >> 8) * 1024 + 512, col = j & 255;
        v = g_puqz[r + col] + expf(g_puqz[r + 256 + col]) * nrm(rbits(kzr0, kzr1, j));
        g_zR[j] = v;
        rrow = NUM_M + (j >> 8); rcol = col;
    } else return;
    g_repf[rrow * 512 + rcol] = __float2half_rn(v);
}

__global__ void k_attn(const float* __restrict__ pg, const int* __restrict__ yM,
                       unsigned k0, unsigned k1) {
    int m = blockIdx.x, r = threadIdx.x;
    __shared__ float um[DD];
    __shared__ float d2s[NUM_R];
    __shared__ float red[NUM_R];
    for (int i = r; i < DD; i += 64) um[i] = g_u[(size_t)(NUM_R + m) * DD + i];
    __syncthreads();
    float d2 = 0.f;
    const float* ur = g_u + (size_t)r * DD;
    for (int dd = 0; dd < DD; dd++) {
        float t = um[dd] - ur[dd];
        d2 = fmaf(t, t, d2);
    }
    d2s[r] = d2;
    float logp = -0.5f * d2 / expf(pg[0]);
    float logit = logp - logf(fmaxf(-expm1f(logp), 1e-20f));
    float U = unif(rbits(k0, k1, (uint32_t)(m * NUM_R + r)));
    float gn = logf(U) - log1pf(-U);
    float A = 1.0f / (1.0f + expf(-(logit + gn) / 0.3f));
    red[r] = A;
    __syncthreads();
    for (int o = 32; o >= 1; o >>= 1) {
        if (r < o) red[r] += red[r + o];
        __syncthreads();
    }
    g_An[m * NUM_R + r] = A / (red[0] + 1e-8f);
    if (r < 32) {
        int idx = r + (1 - yM[m]) * 32;
        float t = sqrtf(fmaxf(d2s[idx], 1e-12f));
        for (int o = 16; o >= 1; o >>= 1) t += __shfl_down_sync(0xffffffffu, t, o);
        if (r == 0) atomicAdd(&g_acc[3], t);
    }
}

__global__ void k_pzq() {
    int m = blockIdx.x, c = threadIdx.x;
    __shared__ float an[NUM_R];
    if (c < NUM_R) an[c] = g_An[m * NUM_R + c];
    __syncthreads();
    float pm = 0.f, pl = 0.f;
    for (int r = 0; r < NUM_R; r++) {
        float a = an[r];
        pm = fmaf(a, g_puqz[r * 1024 + 512 + c], pm);
        pl = fmaf(a, g_puqz[r * 1024 + 768 + c], pl);
    }
    float z = g_zM[m * DD + c];
    int q = (NUM_R + m) * 1024 + 512;
    float qm = g_puqz[q + c], ql = g_puqz[q + 256 + c];
    float t1 = (z - pm) * expf(-pl);
    float t2 = (z - qm) * expf(-ql);
    float v = (-pl - 0.5f * t1 * t1) - (-ql - 0.5f * t2 * t2);
    __shared__ float red[256];
    red[c] = v;
    __syncthreads();
    for (int o = 128; o >= 1; o >>= 1) {
        if (c < o) red[c] += red[c + o];
        __syncthreads();
    }
    if (c == 0) atomicAdd(&g_acc[1], red[0]);
}

__global__ void k_head(const float* __restrict__ hid, const float* __restrict__ W2,
                       const float* __restrict__ b2, const int* __restrict__ yM,
                       const int* __restrict__ yR) {
    int gw = (blockIdx.x * blockDim.x + threadIdx.x) >> 5;
    int lane = threadIdx.x & 31;
    if (gw >= NUM_M + NUM_R) return;
    float p0 = 0.f, p1 = 0.f;
#pragma unroll
    for (int j = 0; j < 8; j++) {
        int k = lane + 32 * j;
        float h = hid[(size_t)gw * 256 + k];
        p0 = fmaf(h, W2[k * 2], p0);
        p1 = fmaf(h, W2[k * 2 + 1], p1);
    }
    for (int o = 16; o >= 1; o >>= 1) {
        p0 += __shfl_down_sync(0xffffffffu, p0, o);
        p1 += __shfl_down_sync(0xffffffffu, p1, o);
    }
    if (lane == 0) {
        float l0 = p0 + b2[0], l1 = p1 + b2[1];
        float mx = fmaxf(l0, l1);
        float lse = mx + logf(expf(l0 - mx) + expf(l1 - mx));
        int y = (gw < NUM_M) ? yM[gw] : yR[gw - NUM_M];
        atomicAdd(&g_acc[(gw < NUM_M) ? 0 : 2], ((y != 0) ? l1 : l0) - lse);
    }
}

__global__ void k_final(float* __restrict__ out) {
    float pred = -(g_acc[0] + 0.1f * g_acc[1]) / 1024.0f;
    float rat  = -g_acc[2] / 64.0f;
    float reg  = g_acc[3] / 32768.0f;
    out[0] = pred + rat - 0.1f * reg;
}

extern "C" void kernel_launch(void* const* d_in, const int* in_sizes, int n_in,
                              void* d_out, int out_size) {
    (void)in_sizes; (void)n_in; (void)out_size;
    const float* x     = (const float*)d_in[0];
    const int*   ei    = (const int*)  d_in[1];
    const int*   et    = (const int*)  d_in[2];
    const int*   batch = (const int*)  d_in[3];
    const int*   yM    = (const int*)  d_in[4];
    const int*   yR    = (const int*)  d_in[5];
    const float* HR    = (const float*)d_in[6];
    const float* nodeW = (const float*)d_in[7];
    const float* nodeB = (const float*)d_in[8];
    const float* Wr    = (const float*)d_in[9];
    const float* Wroot = (const float*)d_in[10];
    const float* gcnB  = (const float*)d_in[11];
    const float* pg    = (const float*)d_in[12];
    const float* puW   = (const float*)d_in[13];
    const float* puB   = (const float*)d_in[14];
    const float* qzW   = (const float*)d_in[15];
    const float* qzB   = (const float*)d_in[16];
    const float* W1    = (const float*)d_in[17];
    const float* b1    = (const float*)d_in[18];
    const float* W2    = (const float*)d_in[19];
    const float* b2    = (const float*)d_in[20];
    float* out = (float*)d_out;

    uint32_t ku0, ku1, ka0, ka1, kzm0, kzm1, kzr0, kzr1;
    tf2x32(0u, 42u, 0u, 0u, ku0, ku1);
    tf2x32(0u, 42u, 0u, 1u, ka0, ka1);
    tf2x32(0u, 42u, 0u, 2u, kzm0, kzm1);
    tf2x32(0u, 42u, 0u, 3u, kzr0, kzr1);

    void* p;
    cudaGetSymbolAddress(&p, g_G);      __half* G    = (__half*)p;
    cudaGetSymbolAddress(&p, g_Wfh);    __half* Wfh = (__half*)p;
    cudaGetSymbolAddress(&p, g_nWfh);   __half* nWfh = (__half*)p;
    cudaGetSymbolAddress(&p, g_xf);     __half* xf = (__half*)p;
    cudaGetSymbolAddress(&p, g_Af);     __half* Af = (__half*)p;
    cudaGetSymbolAddress(&p, g_pqWfh);  __half* pqWfh = (__half*)p;
    cudaGetSymbolAddress(&p, g_pqWfl);  __half* pqWfl = (__half*)p;
    cudaGetSymbolAddress(&p, g_w1fh);   __half* w1fh = (__half*)p;
    cudaGetSymbolAddress(&p, g_w1fl);   __half* w1fl = (__half*)p;
    cudaGetSymbolAddress(&p, g_Hf);     __half* Hf  = (__half*)p;
    cudaGetSymbolAddress(&p, g_repf);   __half* repf = (__half*)p;
    cudaGetSymbolAddress(&p, g_bcat);   float* bcat = (float*)p;
    cudaGetSymbolAddress(&p, g_puqz);   float* puqz = (float*)p;
    cudaGetSymbolAddress(&p, g_hid);    float* hid  = (float*)p;

    static int smem_set = 0;
    if (!smem_set) {
        cudaFuncSetAttribute(k_fmma,  cudaFuncAttributeMaxDynamicSharedMemorySize, 61440);
        cudaFuncSetAttribute(k_fmma2, cudaFuncAttributeMaxDynamicSharedMemorySize, 92160);
        smem_set = 1;
    }

    const int PREP_TOTAL = N_NODES * D_IN + N_LAYERS * GW * 256 + 256 * D_IN +
                           1024 * 256 + 256 * 512 + 1024 + (NUM_M + 1) + NUM_R * DD;

    k_zero_init<<<(N_RELS * N_NODES + 255) / 256, 256>>>();
    k_count<<<(N_EDGES + 255) / 256, 256>>>(ei, et);
    k_scan<<<1, 1024>>>();
    k_scatter<<<(N_EDGES + 255) / 256, 256>>>(ei, et);
    k_prep<<<(PREP_TOTAL + 255) / 256, 256>>>(x, nodeW, Wroot, Wr, puW, qzW, W1,
                                              puB, qzB, batch, HR);

    k_fmma<<<dim3(2, (N_NODES + 127) / 128), 256, 61440>>>(
        xf, nWfh, nodeB, nullptr, Af, N_NODES, 256, D_IN, 0);

    for (int l = 0; l < N_LAYERS; l++) {
        k_fmma<<<dim3(GW / 128, (N_NODES + 127) / 128), 256, 61440>>>(
            Af, Wfh + (size_t)l * GW * 256, nullptr, nullptr, G, N_NODES, GW, 256, 0);
        k_agg<<<(N_NODES * 4 * 32 + 255) / 256, 256>>>(
            gcnB + l * 256, Af, (l < N_LAYERS - 1) ? 1 : 0);
    }

    k_gmean<<<NUM_M, 256>>>();

    k_fmma2<<<dim3(8, HPAD / 128), 256, 92160>>>(
        Hf, pqWfh, pqWfl, bcat, puqz, N_ALL, 1024, 256, 0);

    k_sample_all<<<((N_ALL + NUM_M + NUM_R) * DD + 255) / 256, 256>>>(
        ku0, ku1, kzm0, kzm1, kzr0, kzr1);

    k_attn<<<NUM_M, 64>>>(pg, yM, ka0, ka1);
    k_pzq<<<NUM_M, 256>>>();

    k_fmma2<<<dim3(2, HPAD / 128), 256, 92160>>>(
        repf, w1fh, w1fl, b1, hid, NUM_M + NUM_R, 256, 512, 1);
    k_head<<<((NUM_M + NUM_R) * 32 + 255) / 256, 256>>>(hid, W2, b2, yM, yR);

    k_final<<<1, 1>>>(out);
}

// round 17
// speedup vs baseline: 1.0815x; 1.0815x over previous
#include <cuda_runtime.h>
#include <cuda_bf16.h>
#include <cuda_fp16.h>
#include <stdint.h>
#include <math.h>

#define N_NODES 50000
#define N_EDGES 200000
#define D_IN    128
#define DD      256
#define N_LAYERS 4
#define N_RELS  4
#define NUM_M   1024
#define NUM_R   64
#define N_ALL   (NUM_R + NUM_M)
#define GW      1280
#define MPAD    (N_NODES + 128)
#define HPAD    1152

__device__ __half g_G[(size_t)N_NODES * GW];
__device__ __half g_Wfh[N_LAYERS * GW * 256];
__device__ __half g_nWfh[256 * D_IN];
__device__ __half g_xf[(size_t)MPAD * D_IN];
__device__ __half g_Af[(size_t)MPAD * DD];
__device__ __half g_pqWfh[1024 * 256];
__device__ __half g_pqWfl[1024 * 256];
__device__ __half g_w1fh[256 * 512];
__device__ __half g_w1fl[256 * 512];
__device__ __half g_Hf[HPAD * DD];
__device__ __half g_repf[HPAD * 512];
__device__ float g_bcat[1024];
__device__ int   g_cnt[N_RELS * N_NODES];
__device__ int   g_deg[N_NODES];
__device__ int   g_off[N_NODES + 1];
__device__ int   g_cursor[N_NODES];
__device__ uint2 g_epack[N_EDGES];
__device__ int   g_start[NUM_M + 1];
__device__ float g_puqz[N_ALL * 1024];
__device__ float g_u[N_ALL * DD];
__device__ float g_zM[NUM_M * DD];
__device__ float g_zR[NUM_R * DD];
__device__ float g_An[NUM_M * NUM_R];
__device__ float g_hid[HPAD * 256];
__device__ float g_acc[4];

__host__ __device__ __forceinline__ uint32_t rotl32(uint32_t x, int d) {
    return (x << d) | (x >> (32 - d));
}
__host__ __device__ __forceinline__ void tf2x32(uint32_t k0, uint32_t k1,
                                                uint32_t x0, uint32_t x1,
                                                uint32_t& o0, uint32_t& o1) {
    uint32_t ks2 = k0 ^ k1 ^ 0x1BD11BDAu;
    x0 += k0; x1 += k1;
#define TF_RND(R) { x0 += x1; x1 = rotl32(x1, R); x1 ^= x0; }
    TF_RND(13) TF_RND(15) TF_RND(26) TF_RND(6)
    x0 += k1;  x1 += ks2 + 1u;
    TF_RND(17) TF_RND(29) TF_RND(16) TF_RND(24)
    x0 += ks2; x1 += k0 + 2u;
    TF_RND(13) TF_RND(15) TF_RND(26) TF_RND(6)
    x0 += k0;  x1 += k1 + 3u;
    TF_RND(17) TF_RND(29) TF_RND(16) TF_RND(24)
    x0 += k1;  x1 += ks2 + 4u;
    TF_RND(13) TF_RND(15) TF_RND(26) TF_RND(6)
    x0 += ks2; x1 += k0 + 5u;
#undef TF_RND
    o0 = x0; o1 = x1;
}
__device__ __forceinline__ uint32_t rbits(uint32_t k0, uint32_t k1, uint32_t i) {
    uint32_t o0, o1; tf2x32(k0, k1, 0u, i, o0, o1); return o0 ^ o1;
}
__device__ __forceinline__ float erfinv_xla(float x) {
    float w = -log1pf(-x * x), p;
    if (w < 5.0f) {
        w -= 2.5f;
        p = 2.81022636e-08f;
        p = fmaf(p, w, 3.43273939e-07f);  p = fmaf(p, w, -3.5233877e-06f);
        p = fmaf(p, w, -4.39150654e-06f); p = fmaf(p, w, 0.00021858087f);
        p = fmaf(p, w, -0.00125372503f);  p = fmaf(p, w, -0.00417768164f);
        p = fmaf(p, w, 0.246640727f);     p = fmaf(p, w, 1.50140941f);
    } else {
        w = sqrtf(w) - 3.0f;
        p = -0.000200214257f;
        p = fmaf(p, w, 0.000100950558f);  p = fmaf(p, w, 0.00134934322f);
        p = fmaf(p, w, -0.00367342844f);  p = fmaf(p, w, 0.00573950773f);
        p = fmaf(p, w, -0.0076224613f);   p = fmaf(p, w, 0.00943887047f);
        p = fmaf(p, w, 1.00167406f);      p = fmaf(p, w, 2.83297682f);
    }
    return p * x;
}
__device__ __forceinline__ float u01(uint32_t b) {
    return __uint_as_float((b >> 9) | 0x3f800000u) - 1.0f;
}
__device__ __forceinline__ float nrm(uint32_t b) {
    const float LO = -0.99999994f;
    float v = u01(b) * 2.0f + LO;
    v = fmaxf(LO, v);
    return 1.41421356f * erfinv_xla(v);
}
__device__ __forceinline__ float unif(uint32_t b) {
    const float MN = 1e-06f;
    float v = u01(b) * (0.999999f - MN) + MN;
    return fmaxf(MN, v);
}

__global__ void k_zero_init() {
    int i = blockIdx.x * blockDim.x + threadIdx.x;
    if (i < N_RELS * N_NODES) g_cnt[i] = 0;
    if (i < N_NODES) g_deg[i] = 0;
    if (i < 4) g_acc[i] = 0.0f;
}
__global__ void k_count(const int* __restrict__ ei, const int* __restrict__ et) {
    int e = blockIdx.x * blockDim.x + threadIdx.x;
    if (e >= N_EDGES) return;
    int d = ei[N_EDGES + e];
    atomicAdd(&g_cnt[et[e] * N_NODES + d], 1);
    atomicAdd(&g_deg[d], 1);
}
__global__ void k_scan() {
    __shared__ int part[1024];
    int tid = threadIdx.x;
    const int chunk = (N_NODES + 1023) / 1024;
    int lo = tid * chunk, hi = min(lo + chunk, N_NODES);
    int s = 0;
    for (int i = lo; i < hi; i++) s += g_deg[i];
    part[tid] = s;
    __syncthreads();
    for (int o = 1; o < 1024; o <<= 1) {
        int v = (tid >= o) ? part[tid - o] : 0;
        __syncthreads(); part[tid] += v; __syncthreads();
    }
    int run = part[tid] - s;
    for (int i = lo; i < hi; i++) { g_off[i] = run; g_cursor[i] = run; run += g_deg[i]; }
    if (tid == 1023) g_off[N_NODES] = run;
}
__global__ void k_scatter(const int* __restrict__ ei, const int* __restrict__ et) {
    int e = blockIdx.x * blockDim.x + threadIdx.x;
    if (e >= N_EDGES) return;
    int sn = ei[e], d = ei[N_EDGES + e], r = et[e];
    int p = atomicAdd(&g_cursor[d], 1);
    float inv = 1.0f / (float)g_cnt[r * N_NODES + d];
    g_epack[p] = make_uint2((uint32_t)(sn * GW + 256 + (r << 8)), __float_as_uint(inv));
}

__global__ void k_prep(const float* __restrict__ x, const float* __restrict__ nodeW,
                       const float* __restrict__ Wroot, const float* __restrict__ Wr,
                       const float* __restrict__ puW, const float* __restrict__ qzW,
                       const float* __restrict__ W1, const float* __restrict__ puB,
                       const float* __restrict__ qzB, const int* __restrict__ batch,
                       const float* __restrict__ HR) {
    const int nF = N_NODES * D_IN;
    const int nA = N_LAYERS * GW * 256;
    const int nB = 256 * D_IN;
    const int nC = 1024 * 256;
    const int nE = 256 * 512;
    int i = blockIdx.x * blockDim.x + threadIdx.x;
    if (i < nF) { g_xf[i] = __float2half_rn(x[i]); return; }
    i -= nF;
    if (i < nA) {
        int l = i / (GW * 256), rem = i % (GW * 256);
        int n = rem / 256, k = rem % 256;
        float v;
        if (n < 256) v = Wroot[((size_t)l * 256 + k) * 256 + n];
        else {
            int r = (n >> 8) - 1, h = n & 255;
            v = Wr[(((size_t)l * 4 + r) * 256 + k) * 256 + h];
        }
        g_Wfh[i] = __float2half_rn(v);
        return;
    }
    i -= nA;
    if (i < nB) {
        int n = i / D_IN, k = i % D_IN;
        g_nWfh[i] = __float2half_rn(nodeW[(size_t)k * 256 + n]);
        return;
    }
    i -= nB;
    if (i < nC) {
        int n = i / 256, k = i % 256;
        float v = (n < 512) ? puW[(size_t)k * 512 + n] : qzW[(size_t)k * 512 + (n - 512)];
        __half hi = __float2half_rn(v);
        g_pqWfh[i] = hi;
        g_pqWfl[i] = __float2half_rn(v - __half2float(hi));
        return;
    }
    i -= nC;
    if (i < nE) {
        int n = i / 512, k = i % 512;
        float v = W1[(size_t)k * 256 + n];
        __half hi = __float2half_rn(v);
        g_w1fh[i] = hi;
        g_w1fl[i] = __float2half_rn(v - __half2float(hi));
        return;
    }
    i -= nE;
    if (i < 1024) { g_bcat[i] = (i < 512) ? puB[i] : qzB[i - 512]; return; }
    i -= 1024;
    if (i <= NUM_M) {
        int lo = 0, hi = N_NODES;
        while (lo < hi) { int mid = (lo + hi) >> 1; if (batch[mid] < i) lo = mid + 1; else hi = mid; }
        g_start[i] = lo;
        return;
    }
    i -= (NUM_M + 1);
    if (i < NUM_R * DD) {
        g_Hf[i] = __float2half_rn(fmaxf(HR[i], 0.f));
    }
}

__device__ __forceinline__ void ldm4(uint32_t a, uint32_t& r0, uint32_t& r1,
                                     uint32_t& r2, uint32_t& r3) {
    asm volatile("ldmatrix.sync.aligned.m8n8.x4.shared.b16 {%0,%1,%2,%3}, [%4];"
                 : "=r"(r0), "=r"(r1), "=r"(r2), "=r"(r3) : "r"(a));
}
__device__ __forceinline__ void mma_fp(float* c, const uint32_t* a, const uint32_t* b) {
    asm volatile("mma.sync.aligned.m16n8k16.row.col.f32.f16.f16.f32 "
                 "{%0,%1,%2,%3},{%4,%5,%6,%7},{%8,%9},{%0,%1,%2,%3};"
                 : "+f"(c[0]), "+f"(c[1]), "+f"(c[2]), "+f"(c[3])
                 : "r"(a[0]), "r"(a[1]), "r"(a[2]), "r"(a[3]), "r"(b[0]), "r"(b[1]));
}
__device__ __forceinline__ void cp16(uint32_t dst, const void* src) {
    asm volatile("cp.async.cg.shared.global [%0], [%1], 16;" :: "r"(dst), "l"(src));
}

// ===== fp16 1-term GEMM, BM=BN=128, BK=32, 3 stages, 2 CTA/SM =====
#define LOAD_STAGE_F(s, kq)                                            \
    do {                                                               \
        uint32_t st_ = smq + (s) * 20480;                              \
        _Pragma("unroll")                                              \
        for (int q_ = 0; q_ < 2; q_++) {                               \
            int col_ = (c0 + q_) * 8;                                  \
            uint32_t dd_ = st_ + (row * 40 + col_) * 2;                \
            cp16(dd_,         Agf + (kq) + col_);                      \
            cp16(dd_ + 10240, Bgh + (kq) + col_);                      \
        }                                                              \
    } while (0)

__global__ void __launch_bounds__(256, 2)
k_fmma(const __half* __restrict__ Af, const __half* __restrict__ Bh,
       const float* __restrict__ bias, float* __restrict__ C,
       __half* __restrict__ oF, int M, int N, int K, int relu_out) {
    extern __shared__ __align__(16) __half dsmf[];
    uint32_t smq = (uint32_t)__cvta_generic_to_shared(dsmf);
    int tid = threadIdx.x, lane = tid & 31, wid = tid >> 5;
    int wm = (wid >> 2) * 64, wn = (wid & 3) * 32;
    int bm = blockIdx.y * 128, bn = blockIdx.x * 128;
    int row = tid >> 1, c0 = (tid & 1) * 2;
    const __half* Agf = Af + (size_t)(bm + row) * K;
    const __half* Bgh = Bh + (size_t)(bn + row) * K;

    float acc[4][4][4];
#pragma unroll
    for (int i = 0; i < 4; i++)
#pragma unroll
        for (int j = 0; j < 4; j++)
#pragma unroll
            for (int q = 0; q < 4; q++) acc[i][j][q] = 0.f;

    LOAD_STAGE_F(0, 0);
    asm volatile("cp.async.commit_group;");
    if (32 < K) LOAD_STAGE_F(1, 32);
    asm volatile("cp.async.commit_group;");

    int cur = 0;
    for (int k0 = 0; k0 < K; k0 += 32) {
        int pre = k0 + 64;
        if (pre < K) {
            int s2 = cur + 2; if (s2 >= 3) s2 -= 3;
            LOAD_STAGE_F(s2, pre);
        }
        asm volatile("cp.async.commit_group;");
        asm volatile("cp.async.wait_group 2;");
        __syncthreads();
        uint32_t st = smq + cur * 20480;
#pragma unroll
        for (int kk = 0; kk < 32; kk += 16) {
            uint32_t bh[4][2];
            int brow = wn + (lane & 7) + ((lane >> 4) & 1) * 8;
            int bcol = kk + ((lane >> 3) & 1) * 8;
#pragma unroll
            for (int nb = 0; nb < 2; nb++) {
                uint32_t off = ((brow + nb * 16) * 40 + bcol) * 2;
                ldm4(st + 10240 + off, bh[2 * nb][0], bh[2 * nb][1], bh[2 * nb + 1][0], bh[2 * nb + 1][1]);
            }
            int arow = wm + (lane & 7) + ((lane >> 3) & 1) * 8;
            int acol = kk + ((lane >> 4) & 1) * 8;
#pragma unroll
            for (int mf = 0; mf < 4; mf++) {
                uint32_t a[4];
                uint32_t off = ((arow + mf * 16) * 40 + acol) * 2;
                ldm4(st + off, a[0], a[1], a[2], a[3]);
#pragma unroll
                for (int nf = 0; nf < 4; nf++)
                    mma_fp(acc[mf][nf], a, bh[nf]);
            }
        }
        __syncthreads();
        cur++; if (cur >= 3) cur = 0;
    }
#pragma unroll
    for (int mf = 0; mf < 4; mf++)
#pragma unroll
        for (int nf = 0; nf < 4; nf++) {
            int r0 = bm + wm + mf * 16 + (lane >> 2);
            int c0o = bn + wn + nf * 8 + (lane & 3) * 2;
#pragma unroll
            for (int h = 0; h < 2; h++) {
                int r = r0 + h * 8;
                if (r >= M) continue;
                float v0 = acc[mf][nf][2 * h], v1 = acc[mf][nf][2 * h + 1];
                if (bias) { v0 += bias[c0o]; v1 += bias[c0o + 1]; }
                if (relu_out) { v0 = fmaxf(v0, 0.f); v1 = fmaxf(v1, 0.f); }
                if (oF) {
                    *(__half2*)(oF + (size_t)r * N + c0o) = __floats2half2_rn(v0, v1);
                } else {
                    *(float2*)(C + (size_t)r * N + c0o) = make_float2(v0, v1);
                }
            }
        }
}

// ===== fp16 2-term GEMM for tail: A fp16, B hi/lo fp16. BK=32, 3 stages, 2 CTA/SM =====
#define LOAD_STAGE_2(s, kq)                                            \
    do {                                                               \
        uint32_t st_ = sm2 + (s) * 30720;                              \
        _Pragma("unroll")                                              \
        for (int q_ = 0; q_ < 2; q_++) {                               \
            int col_ = (c0 + q_) * 8;                                  \
            uint32_t dd_ = st_ + (row * 40 + col_) * 2;                \
            cp16(dd_,         Agf + (kq) + col_);                      \
            cp16(dd_ + 10240, Bgh + (kq) + col_);                      \
            cp16(dd_ + 20480, Bgl + (kq) + col_);                      \
        }                                                              \
    } while (0)

__global__ void __launch_bounds__(256, 2)
k_fmma2(const __half* __restrict__ Af, const __half* __restrict__ Bh,
        const __half* __restrict__ Bl, const float* __restrict__ bias,
        float* __restrict__ C, int M, int N, int K, int relu_out) {
    extern __shared__ __align__(16) __half dsm2[];
    uint32_t sm2 = (uint32_t)__cvta_generic_to_shared(dsm2);
    int tid = threadIdx.x, lane = tid & 31, wid = tid >> 5;
    int wm = (wid >> 2) * 64, wn = (wid & 3) * 32;
    int bm = blockIdx.y * 128, bn = blockIdx.x * 128;
    int row = tid >> 1, c0 = (tid & 1) * 2;
    const __half* Agf = Af + (size_t)(bm + row) * K;
    const __half* Bgh = Bh + (size_t)(bn + row) * K;
    const __half* Bgl = Bl + (size_t)(bn + row) * K;

    float acc[4][4][4];
#pragma unroll
    for (int i = 0; i < 4; i++)
#pragma unroll
        for (int j = 0; j < 4; j++)
#pragma unroll
            for (int q = 0; q < 4; q++) acc[i][j][q] = 0.f;

    LOAD_STAGE_2(0, 0);
    asm volatile("cp.async.commit_group;");
    if (32 < K) LOAD_STAGE_2(1, 32);
    asm volatile("cp.async.commit_group;");

    int cur = 0;
    for (int k0 = 0; k0 < K; k0 += 32) {
        int pre = k0 + 64;
        if (pre < K) {
            int s2 = cur + 2; if (s2 >= 3) s2 -= 3;
            LOAD_STAGE_2(s2, pre);
        }
        asm volatile("cp.async.commit_group;");
        asm volatile("cp.async.wait_group 2;");
        __syncthreads();
        uint32_t st = sm2 + cur * 30720;
#pragma unroll
        for (int kk = 0; kk < 32; kk += 16) {
            uint32_t bh[4][2], bl[4][2];
            int brow = wn + (lane & 7) + ((lane >> 4) & 1) * 8;
            int bcol = kk + ((lane >> 3) & 1) * 8;
#pragma unroll
            for (int nb = 0; nb < 2; nb++) {
                uint32_t off = ((brow + nb * 16) * 40 + bcol) * 2;
                ldm4(st + 10240 + off, bh[2 * nb][0], bh[2 * nb][1], bh[2 * nb + 1][0], bh[2 * nb + 1][1]);
                ldm4(st + 20480 + off, bl[2 * nb][0], bl[2 * nb][1], bl[2 * nb + 1][0], bl[2 * nb + 1][1]);
            }
            int arow = wm + (lane & 7) + ((lane >> 3) & 1) * 8;
            int acol = kk + ((lane >> 4) & 1) * 8;
#pragma unroll
            for (int mf = 0; mf < 4; mf++) {
                uint32_t a[4];
                uint32_t off = ((arow + mf * 16) * 40 + acol) * 2;
                ldm4(st + off, a[0], a[1], a[2], a[3]);
#pragma unroll
                for (int nf = 0; nf < 4; nf++) {
                    mma_fp(acc[mf][nf], a, bh[nf]);
                    mma_fp(acc[mf][nf], a, bl[nf]);
                }
            }
        }
        __syncthreads();
        cur++; if (cur >= 3) cur = 0;
    }
#pragma unroll
    for (int mf = 0; mf < 4; mf++)
#pragma unroll
        for (int nf = 0; nf < 4; nf++) {
            int r0 = bm + wm + mf * 16 + (lane >> 2);
            int c0o = bn + wn + nf * 8 + (lane & 3) * 2;
#pragma unroll
            for (int h = 0; h < 2; h++) {
                int r = r0 + h * 8;
                if (r >= M) continue;
                float v0 = acc[mf][nf][2 * h], v1 = acc[mf][nf][2 * h + 1];
                if (bias) { v0 += bias[c0o]; v1 += bias[c0o + 1]; }
                if (relu_out) { v0 = fmaxf(v0, 0.f); v1 = fmaxf(v1, 0.f); }
                *(float2*)(C + (size_t)r * N + c0o) = make_float2(v0, v1);
            }
        }
}

__device__ __forceinline__ void up4(uint2 v, float* f) {
    __half2* h = (__half2*)&v;
    float2 a0 = __half22float2(h[0]); f[0] = a0.x; f[1] = a0.y;
    float2 a1 = __half22float2(h[1]); f[2] = a1.x; f[3] = a1.y;
}

// aggregation over fp16 G, 2 warps per node (R15 proven config)
__global__ void k_agg(const float* __restrict__ bias, __half* __restrict__ ofh, int relu) {
    int gw = (blockIdx.x * blockDim.x + threadIdx.x) >> 5;
    int lane = threadIdx.x & 31;
    int d = gw >> 1;
    int half = gw & 1;
    if (d >= N_NODES) return;
    int cb = half * 128 + lane * 4;
    float acc[4];
    {
        uint2 base = *(const uint2*)(g_G + (size_t)d * GW + cb);
        up4(base, acc);
        float4 bb = *(const float4*)(bias + cb);
        acc[0] += bb.x; acc[1] += bb.y; acc[2] += bb.z; acc[3] += bb.w;
    }
    int s = g_off[d], e = g_off[d + 1];
    int i = s;
#define AGG_EDGE(P)                                                     \
    {                                                                   \
        uint2 gv = *(const uint2*)(g_G + (P).x + cb);                   \
        float inv = __uint_as_float((P).y);                             \
        float f[4]; up4(gv, f);                                         \
        acc[0] = fmaf(f[0], inv, acc[0]); acc[1] = fmaf(f[1], inv, acc[1]); \
        acc[2] = fmaf(f[2], inv, acc[2]); acc[3] = fmaf(f[3], inv, acc[3]); \
    }
    for (; i + 8 <= e; i += 8) {
        uint2 p0 = g_epack[i],     p1 = g_epack[i + 1];
        uint2 p2 = g_epack[i + 2], p3 = g_epack[i + 3];
        uint2 p4 = g_epack[i + 4], p5 = g_epack[i + 5];
        uint2 p6 = g_epack[i + 6], p7 = g_epack[i + 7];
        AGG_EDGE(p0) AGG_EDGE(p1) AGG_EDGE(p2) AGG_EDGE(p3)
        AGG_EDGE(p4) AGG_EDGE(p5) AGG_EDGE(p6) AGG_EDGE(p7)
    }
    for (; i < e; i++) {
        uint2 p0 = g_epack[i];
        AGG_EDGE(p0)
    }
#undef AGG_EDGE
    if (relu) {
#pragma unroll
        for (int j = 0; j < 4; j++) acc[j] = fmaxf(acc[j], 0.f);
    }
    uint2 ov;
    __half2* oh = (__half2*)&ov;
    oh[0] = __floats2half2_rn(acc[0], acc[1]);
    oh[1] = __floats2half2_rn(acc[2], acc[3]);
    *(uint2*)(ofh + (size_t)d * DD + cb) = ov;
}

__global__ void k_gmean() {
    int m = blockIdx.x, c = threadIdx.x;
    int s = g_start[m], e = g_start[m + 1];
    float acc = 0.f;
    for (int n = s; n < e; n++) acc += __half2float(g_Af[(size_t)n * DD + c]);
    float v = fmaxf(acc / fmaxf((float)(e - s), 1.0f), 0.f);
    g_Hf[(size_t)(NUM_R + m) * DD + c] = __float2half_rn(v);
}

__global__ void k_sample_all(unsigned ku0, unsigned ku1, unsigned kzm0, unsigned kzm1,
                             unsigned kzr0, unsigned kzr1) {
    int i = blockIdx.x * blockDim.x + threadIdx.x;
    const int NU = N_ALL * DD, NZM = NUM_M * DD, NZR = NUM_R * DD;
    float v;
    int rrow, rcol;
    if (i < NU) {
        int row = i >> 8, col = i & 255;
        v = g_puqz[row * 1024 + col] +
            expf(g_puqz[row * 1024 + 256 + col]) * nrm(rbits(ku0, ku1, i));
        g_u[i] = v;
        rrow = (row < NUM_R) ? (NUM_M + row) : (row - NUM_R);
        rcol = 256 + col;
    } else if (i < NU + NZM) {
        int j = i - NU;
        int m = j >> 8, col = j & 255;
        int r = (NUM_R + m) * 1024 + 512;
        v = g_puqz[r + col] + expf(g_puqz[r + 256 + col]) * nrm(rbits(kzm0, kzm1, j));
        g_zM[j] = v;
        rrow = m; rcol = col;
    } else if (i < NU + NZM + NZR) {
        int j = i - NU - NZM;
        int r = (j >> 8) * 1024 + 512, col = j & 255;
        v = g_puqz[r + col] + expf(g_puqz[r + 256 + col]) * nrm(rbits(kzr0, kzr1, j));
        g_zR[j] = v;
        rrow = NUM_M + (j >> 8); rcol = col;
    } else return;
    g_repf[rrow * 512 + rcol] = __float2half_rn(v);
}

__global__ void k_attn(const float* __restrict__ pg, const int* __restrict__ yM,
                       unsigned k0, unsigned k1) {
    int m = blockIdx.x, r = threadIdx.x;
    __shared__ float um[DD];
    __shared__ float d2s[NUM_R];
    __shared__ float red[NUM_R];
    for (int i = r; i < DD; i += 64) um[i] = g_u[(size_t)(NUM_R + m) * DD + i];
    __syncthreads();
    float d2 = 0.f;
    const float* ur = g_u + (size_t)r * DD;
    for (int dd = 0; dd < DD; dd++) {
        float t = um[dd] - ur[dd];
        d2 = fmaf(t, t, d2);
    }
    d2s[r] = d2;
    float logp = -0.5f * d2 / expf(pg[0]);
    float logit = logp - logf(fmaxf(-expm1f(logp), 1e-20f));
    float U = unif(rbits(k0, k1, (uint32_t)(m * NUM_R + r)));
    float gn = logf(U) - log1pf(-U);
    float A = 1.0f / (1.0f + expf(-(logit + gn) / 0.3f));
    red[r] = A;
    __syncthreads();
    for (int o = 32; o >= 1; o >>= 1) {
        if (r < o) red[r] += red[r + o];
        __syncthreads();
    }
    g_An[m * NUM_R + r] = A / (red[0] + 1e-8f);
    if (r < 32) {
        int idx = r + (1 - yM[m]) * 32;
        float t = sqrtf(fmaxf(d2s[idx], 1e-12f));
        for (int o = 16; o >= 1; o >>= 1) t += __shfl_down_sync(0xffffffffu, t, o);
        if (r == 0) atomicAdd(&g_acc[3], t);
    }
}

__global__ void k_pzq() {
    int m = blockIdx.x, c = threadIdx.x;
    __shared__ float an[NUM_R];
    if (c < NUM_R) an[c] = g_An[m * NUM_R + c];
    __syncthreads();
    float pm = 0.f, pl = 0.f;
    for (int r = 0; r < NUM_R; r++) {
        float a = an[r];
        pm = fmaf(a, g_puqz[r * 1024 + 512 + c], pm);
        pl = fmaf(a, g_puqz[r * 1024 + 768 + c], pl);
    }
    float z = g_zM[m * DD + c];
    int q = (NUM_R + m) * 1024 + 512;
    float qm = g_puqz[q + c], ql = g_puqz[q + 256 + c];
    float t1 = (z - pm) * expf(-pl);
    float t2 = (z - qm) * expf(-ql);
    float v = (-pl - 0.5f * t1 * t1) - (-ql - 0.5f * t2 * t2);
    __shared__ float red[256];
    red[c] = v;
    __syncthreads();
    for (int o = 128; o >= 1; o >>= 1) {
        if (c < o) red[c] += red[c + o];
        __syncthreads();
    }
    if (c == 0) atomicAdd(&g_acc[1], red[0]);
}

__global__ void k_head(const float* __restrict__ hid, const float* __restrict__ W2,
                       const float* __restrict__ b2, const int* __restrict__ yM,
                       const int* __restrict__ yR) {
    int gw = (blockIdx.x * blockDim.x + threadIdx.x) >> 5;
    int lane = threadIdx.x & 31;
    if (gw >= NUM_M + NUM_R) return;
    float p0 = 0.f, p1 = 0.f;
#pragma unroll
    for (int j = 0; j < 8; j++) {
        int k = lane + 32 * j;
        float h = hid[(size_t)gw * 256 + k];
        p0 = fmaf(h, W2[k * 2], p0);
        p1 = fmaf(h, W2[k * 2 + 1], p1);
    }
    for (int o = 16; o >= 1; o >>= 1) {
        p0 += __shfl_down_sync(0xffffffffu, p0, o);
        p1 += __shfl_down_sync(0xffffffffu, p1, o);
    }
    if (lane == 0) {
        float l0 = p0 + b2[0], l1 = p1 + b2[1];
        float mx = fmaxf(l0, l1);
        float lse = mx + logf(expf(l0 - mx) + expf(l1 - mx));
        int y = (gw < NUM_M) ? yM[gw] : yR[gw - NUM_M];
        atomicAdd(&g_acc[(gw < NUM_M) ? 0 : 2], ((y != 0) ? l1 : l0) - lse);
    }
}

__global__ void k_final(float* __restrict__ out) {
    float pred = -(g_acc[0] + 0.1f * g_acc[1]) / 1024.0f;
    float rat  = -g_acc[2] / 64.0f;
    float reg  = g_acc[3] / 32768.0f;
    out[0] = pred + rat - 0.1f * reg;
}

extern "C" void kernel_launch(void* const* d_in, const int* in_sizes, int n_in,
                              void* d_out, int out_size) {
    (void)in_sizes; (void)n_in; (void)out_size;
    const float* x     = (const float*)d_in[0];
    const int*   ei    = (const int*)  d_in[1];
    const int*   et    = (const int*)  d_in[2];
    const int*   batch = (const int*)  d_in[3];
    const int*   yM    = (const int*)  d_in[4];
    const int*   yR    = (const int*)  d_in[5];
    const float* HR    = (const float*)d_in[6];
    const float* nodeW = (const float*)d_in[7];
    const float* nodeB = (const float*)d_in[8];
    const float* Wr    = (const float*)d_in[9];
    const float* Wroot = (const float*)d_in[10];
    const float* gcnB  = (const float*)d_in[11];
    const float* pg    = (const float*)d_in[12];
    const float* puW   = (const float*)d_in[13];
    const float* puB   = (const float*)d_in[14];
    const float* qzW   = (const float*)d_in[15];
    const float* qzB   = (const float*)d_in[16];
    const float* W1    = (const float*)d_in[17];
    const float* b1    = (const float*)d_in[18];
    const float* W2    = (const float*)d_in[19];
    const float* b2    = (const float*)d_in[20];
    float* out = (float*)d_out;

    uint32_t ku0, ku1, ka0, ka1, kzm0, kzm1, kzr0, kzr1;
    tf2x32(0u, 42u, 0u, 0u, ku0, ku1);
    tf2x32(0u, 42u, 0u, 1u, ka0, ka1);
    tf2x32(0u, 42u, 0u, 2u, kzm0, kzm1);
    tf2x32(0u, 42u, 0u, 3u, kzr0, kzr1);

    void* p;
    cudaGetSymbolAddress(&p, g_G);      __half* G    = (__half*)p;
    cudaGetSymbolAddress(&p, g_Wfh);    __half* Wfh = (__half*)p;
    cudaGetSymbolAddress(&p, g_nWfh);   __half* nWfh = (__half*)p;
    cudaGetSymbolAddress(&p, g_xf);     __half* xf = (__half*)p;
    cudaGetSymbolAddress(&p, g_Af);     __half* Af = (__half*)p;
    cudaGetSymbolAddress(&p, g_pqWfh);  __half* pqWfh = (__half*)p;
    cudaGetSymbolAddress(&p, g_pqWfl);  __half* pqWfl = (__half*)p;
    cudaGetSymbolAddress(&p, g_w1fh);   __half* w1fh = (__half*)p;
    cudaGetSymbolAddress(&p, g_w1fl);   __half* w1fl = (__half*)p;
    cudaGetSymbolAddress(&p, g_Hf);     __half* Hf  = (__half*)p;
    cudaGetSymbolAddress(&p, g_repf);   __half* repf = (__half*)p;
    cudaGetSymbolAddress(&p, g_bcat);   float* bcat = (float*)p;
    cudaGetSymbolAddress(&p, g_puqz);   float* puqz = (float*)p;
    cudaGetSymbolAddress(&p, g_hid);    float* hid  = (float*)p;

    static int smem_set = 0;
    if (!smem_set) {
        cudaFuncSetAttribute(k_fmma,  cudaFuncAttributeMaxDynamicSharedMemorySize, 61440);
        cudaFuncSetAttribute(k_fmma2, cudaFuncAttributeMaxDynamicSharedMemorySize, 92160);
        smem_set = 1;
    }

    const int PREP_TOTAL = N_NODES * D_IN + N_LAYERS * GW * 256 + 256 * D_IN +
                           1024 * 256 + 256 * 512 + 1024 + (NUM_M + 1) + NUM_R * DD;

    k_zero_init<<<(N_RELS * N_NODES + 255) / 256, 256>>>();
    k_count<<<(N_EDGES + 255) / 256, 256>>>(ei, et);
    k_scan<<<1, 1024>>>();
    k_scatter<<<(N_EDGES + 255) / 256, 256>>>(ei, et);
    k_prep<<<(PREP_TOTAL + 255) / 256, 256>>>(x, nodeW, Wroot, Wr, puW, qzW, W1,
                                              puB, qzB, batch, HR);

    k_fmma<<<dim3(2, (N_NODES + 127) / 128), 256, 61440>>>(
        xf, nWfh, nodeB, nullptr, Af, N_NODES, 256, D_IN, 0);

    for (int l = 0; l < N_LAYERS; l++) {
        k_fmma<<<dim3(GW / 128, (N_NODES + 127) / 128), 256, 61440>>>(
            Af, Wfh + (size_t)l * GW * 256, nullptr, nullptr, G, N_NODES, GW, 256, 0);
        k_agg<<<(N_NODES * 2 * 32 + 255) / 256, 256>>>(
            gcnB + l * 256, Af, (l < N_LAYERS - 1) ? 1 : 0);
    }

    k_gmean<<<NUM_M, 256>>>();

    k_fmma2<<<dim3(8, HPAD / 128), 256, 92160>>>(
        Hf, pqWfh, pqWfl, bcat, puqz, N_ALL, 1024, 256, 0);

    k_sample_all<<<((N_ALL + NUM_M + NUM_R) * DD + 255) / 256, 256>>>(
        ku0, ku1, kzm0, kzm1, kzr0, kzr1);

    k_attn<<<NUM_M, 64>>>(pg, yM, ka0, ka1);
    k_pzq<<<NUM_M, 256>>>();

    k_fmma2<<<dim3(2, HPAD / 128), 256, 92160>>>(
        repf, w1fh, w1fl, b1, hid, NUM_M + NUM_R, 256, 512, 1);
    k_head<<<((NUM_M + NUM_R) * 32 + 255) / 256, 256>>>(hid, W2, b2, yM, yR);

    k_final<<<1, 1>>>(out);
}